// round 8
// baseline (speedup 1.0000x reference)
#include <cuda_runtime.h>
#include <cuda_fp16.h>
#include <cstdint>

#define MTOT 8192
#define DM   1024
#define DF   4096
#define NH   8

#define LDS_   72                       // smem row stride (elems), 144B
#define STAGE_ELEMS (3*128*LDS_)        // A_hi + A_lo + B tiles per stage
#define SMEM_BYTES (3*STAGE_ELEMS*2)    // 165888

static __device__ __align__(256) __half g_Xs  [(size_t)MTOT*2*DM];   // [hi|lo]
static __device__ __align__(256) __half g_Wis [(size_t)DM*DM];       // W^T fp16
static __device__ __align__(256) __half g_W1s [(size_t)NH*DF*DM];
static __device__ __align__(256) __half g_W2s [(size_t)NH*DM*DF];
static __device__ __align__(256) __half g_HidS[(size_t)MTOT*2*DF];   // [hi|lo]
static __device__ __align__(256) float g_gcomb[(size_t)MTOT*DM];
static __device__ __align__(256) float g_rsproj[4*DM];
static __device__ __align__(256) float g_wts[MTOT*NH];

// ---------------- helpers ----------------
__device__ __forceinline__ uint32_t smem_u32(const void* p){
    uint32_t a;
    asm("{ .reg .u64 t; cvta.to.shared.u64 t, %1; cvt.u32.u64 %0, t; }" : "=r"(a) : "l"(p));
    return a;
}
__device__ __forceinline__ float gelu_f(float v){
    return 0.5f * v * (1.0f + erff(v * 0.7071067811865476f));
}
__device__ __forceinline__ void split2h(float v, float& hi, float& lo){
    hi = __half2float(__float2half_rn(v));
    lo = v - hi;
}
__device__ __forceinline__ void ldm4(uint32_t* r, uint32_t addr){
    asm volatile("ldmatrix.sync.aligned.m8n8.x4.shared.b16 {%0,%1,%2,%3}, [%4];"
                 : "=r"(r[0]), "=r"(r[1]), "=r"(r[2]), "=r"(r[3]) : "r"(addr));
}
__device__ __forceinline__ void mma_f16(float* d, const uint32_t* a, uint32_t b0, uint32_t b1){
    asm volatile("mma.sync.aligned.m16n8k16.row.col.f32.f16.f16.f32 "
                 "{%0,%1,%2,%3}, {%4,%5,%6,%7}, {%8,%9}, {%0,%1,%2,%3};"
                 : "+f"(d[0]), "+f"(d[1]), "+f"(d[2]), "+f"(d[3])
                 : "r"(a[0]), "r"(a[1]), "r"(a[2]), "r"(a[3]), "r"(b0), "r"(b1));
}
#define CP16(dst, src) asm volatile("cp.async.cg.shared.global [%0], [%1], 16;" :: "r"(dst), "l"(src))
#define CP_COMMIT()    asm volatile("cp.async.commit_group;")
#define CP_WAIT1()     asm volatile("cp.async.wait_group 1;" ::: "memory")

// ---------------- prep kernels ----------------
__global__ void split_x_kernel(const float* __restrict__ x){
    const int t = blockIdx.x;
    const float* xr = x + (size_t)t*DM;
    __half* o = g_Xs + (size_t)t*2*DM;
    for (int k = threadIdx.x; k < DM; k += 256){
        float hi, lo; split2h(xr[k], hi, lo);
        o[k]      = __float2half_rn(hi);
        o[DM + k] = __float2half_rn(lo);
    }
}

// W[K,N] fp32 -> Ws[N,K] fp16 (plain transpose + round)
__global__ void transpose_h_kernel(const float* __restrict__ W, __half* __restrict__ Ws,
                                   int K, int N, size_t inStride, size_t outStride){
    __shared__ float tile[32][33];
    const float* Wm = W + inStride * blockIdx.z;
    __half* Om = Ws + outStride * blockIdx.z;
    const int n0 = blockIdx.x*32, k0 = blockIdx.y*32;
    for (int i = threadIdx.y; i < 32; i += 8)
        tile[i][threadIdx.x] = Wm[(size_t)(k0+i)*N + n0 + threadIdx.x];
    __syncthreads();
    for (int i = threadIdx.y; i < 32; i += 8){
        const int n = n0 + i, k = k0 + threadIdx.x;
        Om[(size_t)n*K + k] = __float2half_rn(tile[threadIdx.x][i]);
    }
}

__global__ void rsproj_kernel(const float* __restrict__ rs, const float* __restrict__ Wsm,
                              const float* __restrict__ bs){
    __shared__ float srs[DM];
    const int b = blockIdx.x;
    const int n = blockIdx.y*128 + threadIdx.x;
    for (int i = threadIdx.x; i < DM; i += 128) srs[i] = rs[(size_t)b*DM + i];
    __syncthreads();
    float acc = bs[n];
    for (int k = 0; k < DM; k++) acc = fmaf(srs[k], Wsm[(size_t)k*DM + n], acc);
    g_rsproj[b*DM + n] = acc;
}

__global__ void logits_kernel(const float* __restrict__ Wg, const float* __restrict__ bg,
                              float* __restrict__ wout){
    __shared__ float sW[NH][DM];
    const int tid = threadIdx.x;
    for (int i = tid; i < DM*NH; i += 256) sW[i & (NH-1)][i >> 3] = Wg[i];
    __syncthreads();
    const int warp = tid >> 5, lid = tid & 31;
    const int t = blockIdx.x*8 + warp;
    const float* g = g_gcomb + (size_t)t*DM;
    float a[NH];
    #pragma unroll
    for (int h = 0; h < NH; h++) a[h] = 0.f;
    for (int k = lid; k < DM; k += 32){
        const float gv = g[k];
        #pragma unroll
        for (int h = 0; h < NH; h++) a[h] = fmaf(gv, sW[h][k], a[h]);
    }
    #pragma unroll
    for (int h = 0; h < NH; h++)
        #pragma unroll
        for (int o = 16; o > 0; o >>= 1)
            a[h] += __shfl_xor_sync(0xFFFFFFFFu, a[h], o);
    if (lid == 0){
        float mx = -1e30f;
        #pragma unroll
        for (int h = 0; h < NH; h++){ a[h] += bg[h]; mx = fmaxf(mx, a[h]); }
        float s = 0.f;
        #pragma unroll
        for (int h = 0; h < NH; h++){ a[h] = expf(a[h]-mx); s += a[h]; }
        const float inv = 1.f/s;
        #pragma unroll
        for (int h = 0; h < NH; h++){
            const float w = a[h]*inv;
            g_wts[t*NH + h] = w;
            wout[t*NH + h]  = w;
        }
    }
}

// ---------------- GEMM: D[m,n] = sum_k (Ahi[m,k]+Alo[m,k])*B[n,k] ----------------
// A stored [M, 2*Kb] = [hi | lo], B stored [N, Kb], both K-major fp16.
// 128x128 CTA tile, 8 warps (4m x 2n), 32x64 warp tile, BK=64, 3-stage cp.async.
// EPI 0: gelu(acc + bias[n] + rsproj[batch,n]) -> outF (g_gcomb)
// EPI 1: gelu(acc + bias[n]) -> split [hi|lo] into outS rows (2*DF stride)
// EPI 2: (acc + bias[n]) * wts[t,h] -> outF (store if head==0 else +=)
template<int EPI>
__global__ __launch_bounds__(256)
void mma_kernel(const __half* __restrict__ A,
                const __half* __restrict__ B,
                int Kb,
                const float* __restrict__ bias,
                const float* __restrict__ extra,
                float* __restrict__ outF,
                __half* __restrict__ outS,
                int head)
{
    extern __shared__ __align__(16) __half sm[];
    const int tid = threadIdx.x;
    const int wid = tid >> 5, lane = tid & 31;
    const int wm = wid >> 1, wn = wid & 1;          // 4 warps along m, 2 along n
    const int m0 = blockIdx.y * 128, n0 = blockIdx.x * 128;
    const int Ka = 2*Kb;
    const int nch = Kb >> 6;

    const __half* Ag = A + (size_t)m0 * Ka;
    const __half* Bg = B + (size_t)n0 * Kb;

    // global-load mapping: 8 threads per 128-byte row; 32 rows per pass, 4 passes
    const int grow = tid >> 3;          // 0..31
    const int gcol = (tid & 7) * 8;     // element col: 0,8,...,56

    float acc[2][8][4];
    #pragma unroll
    for (int i = 0; i < 2; i++)
        #pragma unroll
        for (int j = 0; j < 8; j++)
            #pragma unroll
            for (int r = 0; r < 4; r++) acc[i][j][r] = 0.f;

    auto load_stage = [&](int kc, int slot){
        __half* sah = sm + slot * STAGE_ELEMS;
        __half* sal = sah + 128 * LDS_;
        __half* sb  = sal + 128 * LDS_;
        const size_t ko = (size_t)kc * 64;
        #pragma unroll
        for (int r = 0; r < 4; r++){
            const int row = grow + r*32;
            CP16(smem_u32(sah + (size_t)row*LDS_ + gcol), Ag + (size_t)row*Ka + ko + gcol);
            CP16(smem_u32(sal + (size_t)row*LDS_ + gcol), Ag + (size_t)row*Ka + Kb + ko + gcol);
            CP16(smem_u32(sb  + (size_t)row*LDS_ + gcol), Bg + (size_t)row*Kb + ko + gcol);
        }
        CP_COMMIT();
    };

    load_stage(0, 0);
    if (nch > 1) load_stage(1, 1); else CP_COMMIT();

    for (int kc = 0; kc < nch; kc++){
        CP_WAIT1();
        __syncthreads();
        const int slot = kc % 3;
        const __half* sah = sm + slot * STAGE_ELEMS;
        const uint32_t ah = smem_u32(sah + ((size_t)(wm*32 + (lane & 15)))*LDS_ + (lane >> 4)*8);
        const uint32_t al = ah + 128*LDS_*2;
        const uint32_t bb = ah + ((uint32_t)(256 - wm*32 + wn*64))*LDS_*2;   // sb base + warp n offset
        #pragma unroll
        for (int kk = 0; kk < 4; kk++){
            uint32_t afh[2][4], afl[2][4], bf[4][4];
            #pragma unroll
            for (int mt = 0; mt < 2; mt++){
                ldm4(afh[mt], ah + (uint32_t)(mt*16*LDS_)*2 + kk*32);
                ldm4(afl[mt], al + (uint32_t)(mt*16*LDS_)*2 + kk*32);
            }
            #pragma unroll
            for (int g = 0; g < 4; g++)
                ldm4(bf[g], bb + (uint32_t)(g*16*LDS_)*2 + kk*32);
            #pragma unroll
            for (int mt = 0; mt < 2; mt++)
                #pragma unroll
                for (int nt = 0; nt < 8; nt++){
                    mma_f16(acc[mt][nt], afh[mt], bf[nt>>1][nt&1], bf[nt>>1][2 + (nt&1)]);
                    mma_f16(acc[mt][nt], afl[mt], bf[nt>>1][nt&1], bf[nt>>1][2 + (nt&1)]);
                }
        }
        if (kc + 2 < nch) load_stage(kc + 2, (kc + 2) % 3);
        else CP_COMMIT();
    }

    // -------- epilogue --------
    const int lr = lane >> 2, lc = 2 * (lane & 3);
    #pragma unroll
    for (int mt = 0; mt < 2; mt++){
        #pragma unroll
        for (int half = 0; half < 2; half++){
            const int t = m0 + wm*32 + mt*16 + lr + 8*half;
            float gw = 0.f;
            if (EPI == 2) gw = extra[t*NH + head];
            #pragma unroll
            for (int nt = 0; nt < 8; nt++){
                const int c = n0 + wn*64 + nt*8 + lc;
                float v0 = acc[mt][nt][2*half]     + bias[c];
                float v1 = acc[mt][nt][2*half + 1] + bias[c + 1];
                if (EPI == 0){
                    const float* rp = extra + (size_t)(t >> 11)*DM;
                    float2 o; o.x = gelu_f(v0 + rp[c]); o.y = gelu_f(v1 + rp[c+1]);
                    *reinterpret_cast<float2*>(outF + (size_t)t*DM + c) = o;
                } else if (EPI == 1){
                    v0 = gelu_f(v0); v1 = gelu_f(v1);
                    float h0,l0,h1,l1; split2h(v0,h0,l0); split2h(v1,h1,l1);
                    __half2 ph, pl;
                    ph.x = __float2half_rn(h0); ph.y = __float2half_rn(h1);
                    pl.x = __float2half_rn(l0); pl.y = __float2half_rn(l1);
                    __half* rowp = outS + (size_t)t*2*DF + c;
                    *reinterpret_cast<__half2*>(rowp)      = ph;
                    *reinterpret_cast<__half2*>(rowp + DF) = pl;
                } else {
                    float2* po = reinterpret_cast<float2*>(outF + (size_t)t*DM + c);
                    float2 v; v.x = v0 * gw; v.y = v1 * gw;
                    if (head == 0){
                        *po = v;
                    } else {
                        float2 o = *po; o.x += v.x; o.y += v.y; *po = o;
                    }
                }
            }
        }
    }
}

// ---------------- host ----------------
extern "C" void kernel_launch(void* const* d_in, const int* in_sizes, int n_in,
                              void* d_out, int out_size){
    const float* x   = (const float*)d_in[0];
    const float* rs  = (const float*)d_in[1];
    const float* W1  = (const float*)d_in[2];
    const float* b1  = (const float*)d_in[3];
    const float* W2  = (const float*)d_in[4];
    const float* b2  = (const float*)d_in[5];
    const float* Wsm = (const float*)d_in[6];
    const float* bs  = (const float*)d_in[7];
    const float* Wi  = (const float*)d_in[8];
    const float* bi  = (const float*)d_in[9];
    const float* Wg  = (const float*)d_in[10];
    const float* bg  = (const float*)d_in[11];
    float* out = (float*)d_out;

    void *pXs,*pWis,*pW1s,*pW2s,*pHidS,*pGc,*pRp,*pWts;
    cudaGetSymbolAddress(&pXs,  g_Xs);
    cudaGetSymbolAddress(&pWis, g_Wis);
    cudaGetSymbolAddress(&pW1s, g_W1s);
    cudaGetSymbolAddress(&pW2s, g_W2s);
    cudaGetSymbolAddress(&pHidS,g_HidS);
    cudaGetSymbolAddress(&pGc,  g_gcomb);
    cudaGetSymbolAddress(&pRp,  g_rsproj);
    cudaGetSymbolAddress(&pWts, g_wts);

    cudaFuncSetAttribute(mma_kernel<0>, cudaFuncAttributeMaxDynamicSharedMemorySize, SMEM_BYTES);
    cudaFuncSetAttribute(mma_kernel<1>, cudaFuncAttributeMaxDynamicSharedMemorySize, SMEM_BYTES);
    cudaFuncSetAttribute(mma_kernel<2>, cudaFuncAttributeMaxDynamicSharedMemorySize, SMEM_BYTES);

    split_x_kernel<<<MTOT, 256>>>(x);
    transpose_h_kernel<<<dim3(DM/32, DM/32, 1),  dim3(32,8)>>>(Wi, (__half*)pWis, DM, DM, 0, 0);
    transpose_h_kernel<<<dim3(DF/32, DM/32, NH), dim3(32,8)>>>(W1, (__half*)pW1s, DM, DF,
                                                               (size_t)DM*DF, (size_t)DF*DM);
    transpose_h_kernel<<<dim3(DM/32, DF/32, NH), dim3(32,8)>>>(W2, (__half*)pW2s, DF, DM,
                                                               (size_t)DF*DM, (size_t)DM*DF);
    rsproj_kernel<<<dim3(4, DM/128), 128>>>(rs, Wsm, bs);

    // gating GEMM: gelu(x@Wi + bi + rsproj) -> g_gcomb
    mma_kernel<0><<<dim3(DM/128, MTOT/128), 256, SMEM_BYTES>>>(
        (const __half*)pXs, (const __half*)pWis, DM,
        bi, (const float*)pRp, (float*)pGc, nullptr, 0);

    logits_kernel<<<MTOT/8, 256>>>(Wg, bg, out + (size_t)MTOT*DM);

    for (int h = 0; h < NH; h++){
        mma_kernel<1><<<dim3(DF/128, MTOT/128), 256, SMEM_BYTES>>>(
            (const __half*)pXs,
            (const __half*)pW1s + (size_t)h*DF*DM, DM,
            b1 + (size_t)h*DF, nullptr, nullptr, (__half*)pHidS, h);
        mma_kernel<2><<<dim3(DM/128, MTOT/128), 256, SMEM_BYTES>>>(
            (const __half*)pHidS,
            (const __half*)pW2s + (size_t)h*DM*DF, DF,
            b2 + (size_t)h*DM, (const float*)pWts, out, nullptr, h);
    }
}

// round 9
// speedup vs baseline: 1.1276x; 1.1276x over previous
#include <cuda_runtime.h>
#include <cuda_fp16.h>
#include <cstdint>

#define MTOT 8192
#define DM   1024
#define DF   4096
#define NH   8

#define LDS_   72                        // smem row stride (elems), 144B
#define ASLOT  (128*LDS_)                // one A tile (elems)
#define BSLOT  (128*LDS_)                // one B tile (elems)
#define SMEM_BYTES ((3*ASLOT + 2*BSLOT)*2)   // 92160

// A-side buffers are interleaved per 64-col chunk: [hi0|lo0|hi1|lo1|...]
static __device__ __align__(256) __half g_Xs  [(size_t)MTOT*2*DM];
static __device__ __align__(256) __half g_Wis [(size_t)DM*DM];      // W^T fp16 (plain)
static __device__ __align__(256) __half g_W1s [(size_t)NH*DF*DM];
static __device__ __align__(256) __half g_W2s [(size_t)NH*DM*DF];
static __device__ __align__(256) __half g_HidS[(size_t)MTOT*2*DF];
static __device__ __align__(256) float g_gcomb[(size_t)MTOT*DM];
static __device__ __align__(256) float g_rsproj[4*DM];
static __device__ __align__(256) float g_wts[MTOT*NH];

// ---------------- helpers ----------------
__device__ __forceinline__ uint32_t smem_u32(const void* p){
    uint32_t a;
    asm("{ .reg .u64 t; cvta.to.shared.u64 t, %1; cvt.u32.u64 %0, t; }" : "=r"(a) : "l"(p));
    return a;
}
__device__ __forceinline__ float gelu_f(float v){
    return 0.5f * v * (1.0f + erff(v * 0.7071067811865476f));
}
__device__ __forceinline__ void split2h(float v, float& hi, float& lo){
    hi = __half2float(__float2half_rn(v));
    lo = v - hi;
}
__device__ __forceinline__ void ldm4(uint32_t* r, uint32_t addr){
    asm volatile("ldmatrix.sync.aligned.m8n8.x4.shared.b16 {%0,%1,%2,%3}, [%4];"
                 : "=r"(r[0]), "=r"(r[1]), "=r"(r[2]), "=r"(r[3]) : "r"(addr));
}
__device__ __forceinline__ void mma_f16(float* d, const uint32_t* a, uint32_t b0, uint32_t b1){
    asm volatile("mma.sync.aligned.m16n8k16.row.col.f32.f16.f16.f32 "
                 "{%0,%1,%2,%3}, {%4,%5,%6,%7}, {%8,%9}, {%0,%1,%2,%3};"
                 : "+f"(d[0]), "+f"(d[1]), "+f"(d[2]), "+f"(d[3])
                 : "r"(a[0]), "r"(a[1]), "r"(a[2]), "r"(a[3]), "r"(b0), "r"(b1));
}
#define CP16(dst, src) asm volatile("cp.async.cg.shared.global [%0], [%1], 16;" :: "r"(dst), "l"(src))
#define CP_COMMIT()    asm volatile("cp.async.commit_group;")
#define CP_WAIT1()     asm volatile("cp.async.wait_group 1;" ::: "memory")

// ---------------- prep kernels ----------------
__global__ void split_x_kernel(const float* __restrict__ x){
    const int t = blockIdx.x;
    const float* xr = x + (size_t)t*DM;
    __half* o = g_Xs + (size_t)t*2*DM;
    for (int k = threadIdx.x; k < DM; k += 256){
        float hi, lo; split2h(xr[k], hi, lo);
        const int j = k >> 6, c = k & 63;
        o[j*128 + c]      = __float2half_rn(hi);
        o[j*128 + 64 + c] = __float2half_rn(lo);
    }
}

// W[K,N] fp32 -> Ws[N,K] fp16 (plain transpose + round)
__global__ void transpose_h_kernel(const float* __restrict__ W, __half* __restrict__ Ws,
                                   int K, int N, size_t inStride, size_t outStride){
    __shared__ float tile[32][33];
    const float* Wm = W + inStride * blockIdx.z;
    __half* Om = Ws + outStride * blockIdx.z;
    const int n0 = blockIdx.x*32, k0 = blockIdx.y*32;
    for (int i = threadIdx.y; i < 32; i += 8)
        tile[i][threadIdx.x] = Wm[(size_t)(k0+i)*N + n0 + threadIdx.x];
    __syncthreads();
    for (int i = threadIdx.y; i < 32; i += 8){
        const int n = n0 + i, k = k0 + threadIdx.x;
        Om[(size_t)n*K + k] = __float2half_rn(tile[threadIdx.x][i]);
    }
}

__global__ void rsproj_kernel(const float* __restrict__ rs, const float* __restrict__ Wsm,
                              const float* __restrict__ bs){
    __shared__ float srs[DM];
    const int b = blockIdx.x;
    const int n = blockIdx.y*128 + threadIdx.x;
    for (int i = threadIdx.x; i < DM; i += 128) srs[i] = rs[(size_t)b*DM + i];
    __syncthreads();
    float acc = bs[n];
    for (int k = 0; k < DM; k++) acc = fmaf(srs[k], Wsm[(size_t)k*DM + n], acc);
    g_rsproj[b*DM + n] = acc;
}

__global__ void logits_kernel(const float* __restrict__ Wg, const float* __restrict__ bg,
                              float* __restrict__ wout){
    __shared__ float sW[NH][DM];
    const int tid = threadIdx.x;
    for (int i = tid; i < DM*NH; i += 256) sW[i & (NH-1)][i >> 3] = Wg[i];
    __syncthreads();
    const int warp = tid >> 5, lid = tid & 31;
    const int t = blockIdx.x*8 + warp;
    const float* g = g_gcomb + (size_t)t*DM;
    float a[NH];
    #pragma unroll
    for (int h = 0; h < NH; h++) a[h] = 0.f;
    for (int k = lid; k < DM; k += 32){
        const float gv = g[k];
        #pragma unroll
        for (int h = 0; h < NH; h++) a[h] = fmaf(gv, sW[h][k], a[h]);
    }
    #pragma unroll
    for (int h = 0; h < NH; h++)
        #pragma unroll
        for (int o = 16; o > 0; o >>= 1)
            a[h] += __shfl_xor_sync(0xFFFFFFFFu, a[h], o);
    if (lid == 0){
        float mx = -1e30f;
        #pragma unroll
        for (int h = 0; h < NH; h++){ a[h] += bg[h]; mx = fmaxf(mx, a[h]); }
        float s = 0.f;
        #pragma unroll
        for (int h = 0; h < NH; h++){ a[h] = expf(a[h]-mx); s += a[h]; }
        const float inv = 1.f/s;
        #pragma unroll
        for (int h = 0; h < NH; h++){
            const float w = a[h]*inv;
            g_wts[t*NH + h] = w;
            wout[t*NH + h]  = w;
        }
    }
}

// ---------------- GEMM: D[m,n] = sum_k (Ahi[m,k]+Alo[m,k])*B[n,k] ----------------
// A: [M, 2*Kb] interleaved 64-chunks [hi|lo]; B: [N, Kb]; both K-major fp16.
// 128x128 CTA tile, 8 warps (2m x 4n), 64x32 warp tile, BK=64 per A-chunk.
// A chunks: nch = 2*Kb/64; chunk kc uses B k-block kc>>1 (B loaded on even kc, 2-slot ring).
// EPI 0: gelu(acc + bias[n] + rsproj[batch,n]) -> outF (g_gcomb)
// EPI 1: gelu(acc + bias[n]) -> split interleaved [hi|lo] chunks into outS rows (2*DF)
// EPI 2: (acc + bias[n]) * wts[t,h] -> outF (store if head==0 else +=)
template<int EPI>
__global__ __launch_bounds__(256)
void mma_kernel(const __half* __restrict__ A,
                const __half* __restrict__ B,
                int Kb,
                const float* __restrict__ bias,
                const float* __restrict__ extra,
                float* __restrict__ outF,
                __half* __restrict__ outS,
                int head)
{
    extern __shared__ __align__(16) __half sm[];
    __half* smA = sm;                    // 3 slots
    __half* smB = sm + 3*ASLOT;          // 2 slots
    const int tid = threadIdx.x;
    const int wid = tid >> 5, lane = tid & 31;
    const int wm = wid >> 2, wn = wid & 3;
    const int m0 = blockIdx.y * 128, n0 = blockIdx.x * 128;
    const int Ka = 2*Kb;
    const int nch = Ka >> 6;

    const __half* Ag = A + (size_t)m0 * Ka;
    const __half* Bg = B + (size_t)n0 * Kb;

    const int grow = tid >> 3;          // 0..31
    const int gcol = (tid & 7) * 8;     // 0,8,...,56

    float acc[4][4][4];
    #pragma unroll
    for (int i = 0; i < 4; i++)
        #pragma unroll
        for (int j = 0; j < 4; j++)
            #pragma unroll
            for (int r = 0; r < 4; r++) acc[i][j][r] = 0.f;

    auto load_stage = [&](int kc){
        __half* sa = smA + (kc % 3) * ASLOT;
        const size_t ko = (size_t)kc * 64;
        #pragma unroll
        for (int r = 0; r < 4; r++){
            const int row = grow + r*32;
            CP16(smem_u32(sa + (size_t)row*LDS_ + gcol), Ag + (size_t)row*Ka + ko + gcol);
        }
        if ((kc & 1) == 0){
            __half* sb = smB + ((kc >> 1) & 1) * BSLOT;
            const size_t kob = (size_t)(kc >> 1) * 64;
            #pragma unroll
            for (int r = 0; r < 4; r++){
                const int row = grow + r*32;
                CP16(smem_u32(sb + (size_t)row*LDS_ + gcol), Bg + (size_t)row*Kb + kob + gcol);
            }
        }
        CP_COMMIT();
    };

    load_stage(0);
    if (nch > 1) load_stage(1); else CP_COMMIT();

    for (int kc = 0; kc < nch; kc++){
        CP_WAIT1();
        __syncthreads();
        const __half* sa = smA + (kc % 3) * ASLOT;
        const __half* sb = smB + ((kc >> 1) & 1) * BSLOT;
        const uint32_t abase = smem_u32(sa + ((size_t)(wm*64 + (lane & 15)))*LDS_ + (lane >> 4)*8);
        const uint32_t bbase = smem_u32(sb + ((size_t)(wn*32 + (lane & 15)))*LDS_ + (lane >> 4)*8);
        #pragma unroll
        for (int kk = 0; kk < 4; kk++){
            uint32_t af[4][4], bf[2][4];
            #pragma unroll
            for (int mt = 0; mt < 4; mt++)
                ldm4(af[mt], abase + (uint32_t)(mt*16*LDS_)*2 + kk*32);
            #pragma unroll
            for (int g = 0; g < 2; g++)
                ldm4(bf[g], bbase + (uint32_t)(g*16*LDS_)*2 + kk*32);
            #pragma unroll
            for (int mt = 0; mt < 4; mt++)
                #pragma unroll
                for (int nt = 0; nt < 4; nt++)
                    mma_f16(acc[mt][nt], af[mt], bf[nt>>1][nt&1], bf[nt>>1][2 + (nt&1)]);
        }
        if (kc + 2 < nch) load_stage(kc + 2);
        else CP_COMMIT();
    }

    // -------- epilogue --------
    const int lr = lane >> 2, lc = 2 * (lane & 3);
    #pragma unroll
    for (int mt = 0; mt < 4; mt++){
        #pragma unroll
        for (int half = 0; half < 2; half++){
            const int t = m0 + wm*64 + mt*16 + lr + 8*half;
            float gw = 0.f;
            if (EPI == 2) gw = extra[t*NH + head];
            #pragma unroll
            for (int nt = 0; nt < 4; nt++){
                const int c = n0 + wn*32 + nt*8 + lc;
                float v0 = acc[mt][nt][2*half]     + bias[c];
                float v1 = acc[mt][nt][2*half + 1] + bias[c + 1];
                if (EPI == 0){
                    const float* rp = extra + (size_t)(t >> 11)*DM;
                    float2 o; o.x = gelu_f(v0 + rp[c]); o.y = gelu_f(v1 + rp[c+1]);
                    *reinterpret_cast<float2*>(outF + (size_t)t*DM + c) = o;
                } else if (EPI == 1){
                    v0 = gelu_f(v0); v1 = gelu_f(v1);
                    float h0,l0,h1,l1; split2h(v0,h0,l0); split2h(v1,h1,l1);
                    __half2 ph, pl;
                    ph.x = __float2half_rn(h0); ph.y = __float2half_rn(h1);
                    pl.x = __float2half_rn(l0); pl.y = __float2half_rn(l1);
                    const int j = c >> 6, cc = c & 63;
                    __half* rowp = outS + (size_t)t*2*DF + (size_t)j*128 + cc;
                    *reinterpret_cast<__half2*>(rowp)      = ph;
                    *reinterpret_cast<__half2*>(rowp + 64) = pl;
                } else {
                    float2* po = reinterpret_cast<float2*>(outF + (size_t)t*DM + c);
                    float2 v; v.x = v0 * gw; v.y = v1 * gw;
                    if (head == 0){
                        *po = v;
                    } else {
                        float2 o = *po; o.x += v.x; o.y += v.y; *po = o;
                    }
                }
            }
        }
    }
}

// ---------------- host ----------------
extern "C" void kernel_launch(void* const* d_in, const int* in_sizes, int n_in,
                              void* d_out, int out_size){
    const float* x   = (const float*)d_in[0];
    const float* rs  = (const float*)d_in[1];
    const float* W1  = (const float*)d_in[2];
    const float* b1  = (const float*)d_in[3];
    const float* W2  = (const float*)d_in[4];
    const float* b2  = (const float*)d_in[5];
    const float* Wsm = (const float*)d_in[6];
    const float* bs  = (const float*)d_in[7];
    const float* Wi  = (const float*)d_in[8];
    const float* bi  = (const float*)d_in[9];
    const float* Wg  = (const float*)d_in[10];
    const float* bg  = (const float*)d_in[11];
    float* out = (float*)d_out;

    void *pXs,*pWis,*pW1s,*pW2s,*pHidS,*pGc,*pRp,*pWts;
    cudaGetSymbolAddress(&pXs,  g_Xs);
    cudaGetSymbolAddress(&pWis, g_Wis);
    cudaGetSymbolAddress(&pW1s, g_W1s);
    cudaGetSymbolAddress(&pW2s, g_W2s);
    cudaGetSymbolAddress(&pHidS,g_HidS);
    cudaGetSymbolAddress(&pGc,  g_gcomb);
    cudaGetSymbolAddress(&pRp,  g_rsproj);
    cudaGetSymbolAddress(&pWts, g_wts);

    cudaFuncSetAttribute(mma_kernel<0>, cudaFuncAttributeMaxDynamicSharedMemorySize, SMEM_BYTES);
    cudaFuncSetAttribute(mma_kernel<1>, cudaFuncAttributeMaxDynamicSharedMemorySize, SMEM_BYTES);
    cudaFuncSetAttribute(mma_kernel<2>, cudaFuncAttributeMaxDynamicSharedMemorySize, SMEM_BYTES);

    split_x_kernel<<<MTOT, 256>>>(x);
    transpose_h_kernel<<<dim3(DM/32, DM/32, 1),  dim3(32,8)>>>(Wi, (__half*)pWis, DM, DM, 0, 0);
    transpose_h_kernel<<<dim3(DF/32, DM/32, NH), dim3(32,8)>>>(W1, (__half*)pW1s, DM, DF,
                                                               (size_t)DM*DF, (size_t)DF*DM);
    transpose_h_kernel<<<dim3(DM/32, DF/32, NH), dim3(32,8)>>>(W2, (__half*)pW2s, DF, DM,
                                                               (size_t)DF*DM, (size_t)DM*DF);
    rsproj_kernel<<<dim3(4, DM/128), 128>>>(rs, Wsm, bs);

    // gating GEMM: gelu(x@Wi + bi + rsproj) -> g_gcomb
    mma_kernel<0><<<dim3(DM/128, MTOT/128), 256, SMEM_BYTES>>>(
        (const __half*)pXs, (const __half*)pWis, DM,
        bi, (const float*)pRp, (float*)pGc, nullptr, 0);

    logits_kernel<<<MTOT/8, 256>>>(Wg, bg, out + (size_t)MTOT*DM);

    for (int h = 0; h < NH; h++){
        mma_kernel<1><<<dim3(DF/128, MTOT/128), 256, SMEM_BYTES>>>(
            (const __half*)pXs,
            (const __half*)pW1s + (size_t)h*DF*DM, DM,
            b1 + (size_t)h*DF, nullptr, nullptr, (__half*)pHidS, h);
        mma_kernel<2><<<dim3(DM/128, MTOT/128), 256, SMEM_BYTES>>>(
            (const __half*)pHidS,
            (const __half*)pW2s + (size_t)h*DM*DF, DF,
            b2 + (size_t)h*DM, (const float*)pWts, out, nullptr, h);
    }
}